// round 12
// baseline (speedup 1.0000x reference)
#include <cuda_runtime.h>

// CRF Viterbi decode: B=1024, T=512, C=48
// inputs: 0=potentials (B,T,C) f32, 1=sequence_lengths (B,1) i32, 2=transitions (C,C) f32
// output: one_hot(tags, C) f32 (B,T,C)
//
// R10: depth-4 register prefetch of potentials (hides ~600-1000cy DRAM latency
// that was fully exposed per forward step). Scheduler/math unchanged from R9.

#define BB   1024
#define TT   512
#define CC   48
#define HALF 24
#define NTH  (2 * CC)      // 96
#define NBLK 592           // 4 blocks per SM on 148-SM GB300

__device__ int g_order[BB];
__device__ int g_counter;

// two independent round-to-nearest fp32 adds in one instruction (bitwise == FADD.RN)
__device__ __forceinline__ void addf32x2(float &o0, float &o1,
                                         float a0, float a1,
                                         float b0, float b1)
{
    asm("{\n\t"
        ".reg .b64 ra, rb, rc;\n\t"
        "mov.b64 ra, {%2,%3};\n\t"
        "mov.b64 rb, {%4,%5};\n\t"
        "add.rn.f32x2 rc, ra, rb;\n\t"
        "mov.b64 {%0,%1}, rc;\n\t"
        "}"
        : "=f"(o0), "=f"(o1)
        : "f"(a0), "f"(a1), "f"(b0), "f"(b1));
}

// Counting sort of batch ids by descending sequence length; resets counter.
__global__ void order_kernel(const int* __restrict__ seq_len)
{
    __shared__ int hist[TT];
    __shared__ int offs[TT];
    const int tid = threadIdx.x;        // 512 threads

    hist[tid] = 0;
    __syncthreads();

    for (int b = tid; b < BB; b += TT) {
        int L = seq_len[b];
        if (L < 0) L = 0;
        if (L > TT - 1) L = TT - 1;
        atomicAdd(&hist[L], 1);
    }
    __syncthreads();

    if (tid == 0) {
        int acc = 0;
        for (int L = TT - 1; L >= 0; --L) { offs[L] = acc; acc += hist[L]; }
        g_counter = 0;
    }
    __syncthreads();

    for (int b = tid; b < BB; b += TT) {
        int L = seq_len[b];
        if (L < 0) L = 0;
        if (L > TT - 1) L = TT - 1;
        int pos = atomicAdd(&offs[L], 1);
        g_order[pos] = b;
    }
}

__global__ __launch_bounds__(NTH, 8)
void viterbi_kernel(const float* __restrict__ pot,
                    const int*   __restrict__ seq_len,
                    const float* __restrict__ trans,
                    float*       __restrict__ out)
{
    __shared__ float         s_score[2][CC];
    __shared__ unsigned char s_bp[(TT - 1) * CC];   // bp[t-1][j]
    __shared__ unsigned char s_tags[TT];
    __shared__ int           s_lasttag;
    __shared__ int           s_batch;

    const int tid = threadIdx.x;
    const int j   = tid >> 1;    // class owned by this pair
    const int h   = tid & 1;     // which half of the sources

    // this thread's 24 transition values: trans[h*24+k][j] (loop-invariant)
    float c[HALF];
#pragma unroll
    for (int k = 0; k < HALF; ++k)
        c[k] = trans[(h * HALF + k) * CC + j];

    for (;;) {
        __syncthreads();                       // protect s_batch / smem reuse
        if (tid == 0) s_batch = atomicAdd(&g_counter, 1);
        __syncthreads();
        const int n = s_batch;
        if (n >= BB) break;                    // uniform exit
        const int b = g_order[n];

        const float* potb = pot + (size_t)b * TT * CC;
        int L = seq_len[b];
        if (L > TT) L = TT;
        if (L < 1)  L = 1;

        if (h == 0) s_score[0][j] = potb[j];

        // depth-4 prefetch pipeline for potentials (clamped: always in-bounds)
        float p0 = potb[(1 < TT ? 1 : TT - 1) * CC + j];
        float p1 = potb[(2 < TT ? 2 : TT - 1) * CC + j];
        float p2 = potb[(3 < TT ? 3 : TT - 1) * CC + j];
        float p3 = potb[(4 < TT ? 4 : TT - 1) * CC + j];
        __syncthreads();

        int buf = 0;
        for (int t = 1; t < L; ++t) {
            float pv = p0;
            // shift pipeline, launch load for t+4 (4 loads in flight)
            p0 = p1; p1 = p2; p2 = p3;
            int tl = t + 4; if (tl > TT - 1) tl = TT - 1;
            p3 = potb[tl * CC + j];

            // this thread's 24 scores (96-byte-aligned float4 loads)
            float sc[HALF];
            const float4* s4 = reinterpret_cast<const float4*>(&s_score[buf][h * HALF]);
#pragma unroll
            for (int q = 0; q < HALF / 4; ++q) {
                float4 v4 = s4[q];
                sc[4 * q + 0] = v4.x; sc[4 * q + 1] = v4.y;
                sc[4 * q + 2] = v4.z; sc[4 * q + 3] = v4.w;
            }

            // sums via packed f32x2 adds
            float v[HALF];
#pragma unroll
            for (int q = 0; q < HALF / 2; ++q)
                addf32x2(v[2 * q], v[2 * q + 1],
                         sc[2 * q], sc[2 * q + 1],
                         c[2 * q],  c[2 * q + 1]);

            // local argmax tree 24->12->6->3->1; strict '>' on the
            // higher-index side => first-max-wins
            float val[12]; int id[12];
#pragma unroll
            for (int q = 0; q < 12; ++q) {
                bool p = v[2 * q + 1] > v[2 * q];
                val[q] = p ? v[2 * q + 1] : v[2 * q];
                id[q]  = p ? (2 * q + 1) : (2 * q);
            }
#pragma unroll
            for (int q = 0; q < 6; ++q) {
                bool p = val[2 * q + 1] > val[2 * q];
                val[q] = p ? val[2 * q + 1] : val[2 * q];
                id[q]  = p ? id[2 * q + 1]  : id[2 * q];
            }
#pragma unroll
            for (int q = 0; q < 3; ++q) {
                bool p = val[2 * q + 1] > val[2 * q];
                val[q] = p ? val[2 * q + 1] : val[2 * q];
                id[q]  = p ? id[2 * q + 1]  : id[2 * q];
            }
            bool  p1b = val[1] > val[0];
            float mv = p1b ? val[1] : val[0];
            int   ma = p1b ? id[1]  : id[0];
            bool  p2b = val[2] > mv;
            mv = p2b ? val[2] : mv;
            ma = p2b ? id[2]  : ma;
            ma += h * HALF;                 // globalize index

            // combine the two halves (pair lanes 2j,2j+1: same warp)
            float ov = __shfl_xor_sync(0xFFFFFFFFu, mv, 1);
            int   oa = __shfl_xor_sync(0xFFFFFFFFu, ma, 1);

            float lo_v = h ? ov : mv;  int lo_a = h ? oa : ma;
            float hi_v = h ? mv : ov;  int hi_a = h ? ma : oa;
            bool  p  = hi_v > lo_v;
            float bv = p ? hi_v : lo_v;
            int   bi = p ? hi_a : lo_a;

            if (h) s_score[buf ^ 1][j]    = bv + pv;
            else   s_bp[(t - 1) * CC + j] = (unsigned char)bi;
            buf ^= 1;
            __syncthreads();   // ping-pong: one barrier per step
        }

        // final argmax over last score (first-max wins)
        if (tid == 0) {
            float bestv = s_score[buf][0];
            int tag = 0;
#pragma unroll
            for (int i = 1; i < CC; ++i) {
                float v = s_score[buf][i];
                if (v > bestv) { bestv = v; tag = i; }
            }
            s_lasttag = tag;
        }
        __syncthreads();

        const int tag0 = s_lasttag;
        // parallel fill of the identity tail
        for (int t = L - 1 + tid; t < TT; t += NTH) s_tags[t] = (unsigned char)tag0;

        // serial backtrack (shared-mem pointer chase)
        if (tid == 0) {
            int tag = tag0;
            for (int t = L - 1; t >= 1; --t) {
                tag = s_bp[(t - 1) * CC + tag];
                s_tags[t - 1] = (unsigned char)tag;
            }
        }
        __syncthreads();

        // one-hot output: float4 stores, coalesced
        float4* ob = reinterpret_cast<float4*>(out + (size_t)b * TT * CC);
        const int NQ = TT * (CC / 4);   // 6144 quads per batch row
        for (int q = tid; q < NQ; q += NTH) {
            int t   = q / (CC / 4);
            int r   = q % (CC / 4);
            int tag = s_tags[t];
            int e   = r * 4;
            float4 v;
            v.x = (e + 0 == tag) ? 1.0f : 0.0f;
            v.y = (e + 1 == tag) ? 1.0f : 0.0f;
            v.z = (e + 2 == tag) ? 1.0f : 0.0f;
            v.w = (e + 3 == tag) ? 1.0f : 0.0f;
            ob[q] = v;
        }
    }
}

extern "C" void kernel_launch(void* const* d_in, const int* in_sizes, int n_in,
                              void* d_out, int out_size)
{
    const float* pot    = (const float*)d_in[0];
    const int*   seqlen = (const int*)d_in[1];
    const float* trans  = (const float*)d_in[2];
    float*       out    = (float*)d_out;

    order_kernel<<<1, TT>>>(seqlen);
    viterbi_kernel<<<NBLK, NTH>>>(pot, seqlen, trans, out);
}